// round 15
// baseline (speedup 1.0000x reference)
#include <cuda_runtime.h>
#include <cuda_bf16.h>
#include <cstdint>

#define BB    8192
#define CC    1024
#define NCLS  100
#define CAP   1024
#define NQ    4          // column quarters for the reduce kernel
#define TINV  0.25f      // 1/T, T=4
#define PSCALE 128.0f    // fp8 storage scale: q = p*128 keeps q in e4m3 normal range

// ---- scratch (device globals: no allocations allowed) ----
__device__ uint8_t g_p8[(size_t)BB * CC];         // 8 MB fp8(e4m3) scaled probs
__device__ float g_t[BB];
__device__ int   g_cnt[NCLS];
__device__ int   g_list[NCLS * CAP];
__device__ float g_partial[NCLS * NQ];
__device__ int   g_done = 0;                      // reset by last CTA each run

// ---- helpers ----
__device__ __forceinline__ uint32_t pack4_e4m3(float p0, float p1, float p2, float p3) {
  uint16_t lo, hi;
  asm("cvt.rn.satfinite.e4m3x2.f32 %0, %1, %2;" : "=h"(lo) : "f"(p1), "f"(p0));
  asm("cvt.rn.satfinite.e4m3x2.f32 %0, %1, %2;" : "=h"(hi) : "f"(p3), "f"(p2));
  return (uint32_t)lo | ((uint32_t)hi << 16);
}

// 4 e4m3 bytes (one uint32) -> 4 floats. Exact: e4m3 -> f16 -> f32.
// Column-order permutation inside the word is irrelevant (all uses are
// column-symmetric sums with consistent s/u pairing).
__device__ __forceinline__ void cvt4_e4m3(float* f, uint32_t w) {
  uint32_t h0, h1;
  asm("cvt.rn.f16x2.e4m3x2 %0, %1;" : "=r"(h0) : "h"((uint16_t)(w & 0xffff)));
  asm("cvt.rn.f16x2.e4m3x2 %0, %1;" : "=r"(h1) : "h"((uint16_t)(w >> 16)));
  asm("{.reg .f16 l, h; mov.b32 {l, h}, %2; cvt.f32.f16 %0, l; cvt.f32.f16 %1, h;}"
      : "=f"(f[0]), "=f"(f[1]) : "r"(h0));
  asm("{.reg .f16 l, h; mov.b32 {l, h}, %2; cvt.f32.f16 %0, l; cvt.f32.f16 %1, h;}"
      : "=f"(f[2]), "=f"(f[3]) : "r"(h1));
}

__device__ __forceinline__ float warpMaxf(float v) {
#pragma unroll
  for (int o = 16; o > 0; o >>= 1) v = fmaxf(v, __shfl_xor_sync(0xffffffffu, v, o));
  return v;
}
__device__ __forceinline__ float warpSumf(float v) {
#pragma unroll
  for (int o = 16; o > 0; o >>= 1) v += __shfl_xor_sync(0xffffffffu, v, o);
  return v;
}

// exp(z) for z <= 0 via 2^w with degree-7 poly: FMA pipe only, avoids MUFU.EX2.
__device__ __forceinline__ float fast_exp(float z) {
  float w  = z * 1.4426950408889634f;
  float nf = floorf(w);
  float f  = w - nf;
  float r  = 1.5252733e-5f;
  r = fmaf(r, f, 1.5403530e-4f);
  r = fmaf(r, f, 1.3333558e-3f);
  r = fmaf(r, f, 9.6181291e-3f);
  r = fmaf(r, f, 5.5504109e-2f);
  r = fmaf(r, f, 2.4022651e-1f);
  r = fmaf(r, f, 6.9314718e-1f);
  r = fmaf(r, f, 1.0f);
  return r * __int_as_float(((int)nf + 127) << 23);
}

// ---- setup (runs inside softmax CTA 0): dtype probe + class scatter ----
// JAX with x64 disabled silently stores int64-requested targets as int32.
// True LE int64 in [0,100) => every odd 32-bit word of the first BB words is 0.
__device__ __forceinline__ void do_setup(const int* __restrict__ tgt32, int tid) {
  __shared__ int scnt[NCLS];
  __shared__ int nz;
  for (int i = tid; i < NCLS; i += 256) scnt[i] = 0;
  if (tid == 0) nz = 0;
  __syncthreads();

  int c = 0;
  for (int i = tid; i < BB / 2; i += 256)
    if (tgt32[2 * i + 1] != 0) c++;
  if (c) atomicAdd(&nz, 1);
  __syncthreads();
  int stride = (nz == 0) ? 2 : 1;   // 2 => int64 low words

  for (int i = tid; i < BB; i += 256) {
    int cl = tgt32[(size_t)i * stride];
    if ((unsigned)cl < NCLS) {
      int s = atomicAdd(&scnt[cl], 1);
      if (s < CAP) g_list[cl * CAP + s] = i;
    }
  }
  __syncthreads();
  for (int i = tid; i < NCLS; i += 256) g_cnt[i] = scnt[i];
}

// ---------------- softmax + t (warp per row) + embedded setup in CTA 0 ----------------
__global__ void __launch_bounds__(256) softmax_kernel(const float* __restrict__ x,
                                                      const int* __restrict__ tgt32) {
  if (blockIdx.x == 0) do_setup(tgt32, threadIdx.x);

  int wid = threadIdx.x >> 5, lid = threadIdx.x & 31;
  int row = blockIdx.x * 8 + wid;

  const float4* src = reinterpret_cast<const float4*>(x + (size_t)row * CC);
  float y[32];
  float m = -3.4e38f;
#pragma unroll
  for (int q = 0; q < 8; q++) {
    float4 v = src[q * 32 + lid];
    y[4 * q + 0] = v.x * TINV; y[4 * q + 1] = v.y * TINV;
    y[4 * q + 2] = v.z * TINV; y[4 * q + 3] = v.w * TINV;
    m = fmaxf(m, fmaxf(fmaxf(y[4 * q], y[4 * q + 1]), fmaxf(y[4 * q + 2], y[4 * q + 3])));
  }
  m = warpMaxf(m);

  float e[32];
  float s = 0.0f;
#pragma unroll
  for (int i = 0; i < 32; i++) { e[i] = fast_exp(y[i] - m); s += e[i]; }
  s = warpSumf(s);
  float invS = 1.0f / s;
  float lnS  = __logf(s);

  uint32_t* dst = reinterpret_cast<uint32_t*>(g_p8 + (size_t)row * CC);
  float tl = 0.0f;
#pragma unroll
  for (int q = 0; q < 8; q++) {
    float p0 = fmaf(e[4 * q + 0], invS, 1e-8f);
    float p1 = fmaf(e[4 * q + 1], invS, 1e-8f);
    float p2 = fmaf(e[4 * q + 2], invS, 1e-8f);
    float p3 = fmaf(e[4 * q + 3], invS, 1e-8f);
    // log p ~= y - m - lnS (+1e-8 shift perturbs log by ~1e-5 abs -> negligible)
    tl += p0 * (y[4 * q + 0] - m - lnS) + p1 * (y[4 * q + 1] - m - lnS)
        + p2 * (y[4 * q + 2] - m - lnS) + p3 * (y[4 * q + 3] - m - lnS);
    dst[q * 32 + lid] = pack4_e4m3(p0 * PSCALE, p1 * PSCALE, p2 * PSCALE, p3 * PSCALE);
  }
  tl = warpSumf(tl);
  if (lid == 0) g_t[row] = tl * (1.0f / CC);
}

// ------------- per-(class, column-quarter) linearized loss + fused final reduce ------
// Loss per class over ordered same-label pairs (i != j):
//   sum (t_j - cross_ij)^2 = (g-1)*sum t^2 - (2/C)*( s.u - sum_j t_j*||p_j||^2 )
//                            [ + sum cross^2, ~2e-8 rel: dropped ]
// grid = (NCLS, NQ); CTA (c, by) owns 256 columns. Lane layout: lanes 0-15 of a
// warp cover one row's quarter with ONE uint4 (16 fp8 cols), lanes 16-31 a second
// row; 16 warps -> 32 rows/sweep; all 4 sweeps' gathers issued BEFORE conversion
// (MLP=4, one DRAM round-trip of depth -- the R14 binder was a 10-deep MLP=2 chain).
__global__ void __launch_bounds__(512) reduce_kernel(float* __restrict__ out) {
  int c  = blockIdx.x;
  int by = blockIdx.y;
  int g  = min(g_cnt[c], CAP);

  __shared__ float sS[16][256];   // 16 KB per-warp s partials
  __shared__ float sU[16][256];   // 16 KB
  __shared__ int   sRow[CAP];     // 4 KB
  __shared__ float sTv[CAP];      // 4 KB
  __shared__ float rs[16];
  __shared__ int   sLast;

  int tid = threadIdx.x, wid = tid >> 5, lid = tid & 31;
  int l16 = lid & 15, hi = lid >> 4;
  int rbase = 2 * wid + hi;       // row within a 32-row sweep
  int qidx  = by * 16 + l16;      // uint4 index within the row (64 per row)

  for (int r = tid; r < g; r += 512) {
    int ro = g_list[c * CAP + r];
    sRow[r] = ro;
    sTv[r]  = g_t[ro];
  }
  __syncthreads();

  float sA[16], uA[16];
#pragma unroll
  for (int i = 0; i < 16; i++) { sA[i] = 0.0f; uA[i] = 0.0f; }
  float nrm = 0.0f;               // per-lane partial: sum_j t_j * (lane part ||q_j||^2)

  for (int rb = rbase; rb < g; rb += 128) {
    // batch all 4 gathers (rows rb, rb+32, rb+64, rb+96) before converting
    uint4 wv[4];
    float tv[4];
#pragma unroll
    for (int b = 0; b < 4; b++) {
      int rr = rb + 32 * b;
      bool v = rr < g;
      int ro = v ? sRow[rr] : sRow[0];
      uint4 w = v ? reinterpret_cast<const uint4*>(g_p8 + (size_t)ro * CC)[qidx]
                  : make_uint4(0u, 0u, 0u, 0u);
      wv[b] = w;
      tv[b] = v ? sTv[rr] : 0.0f;
    }
#pragma unroll
    for (int b = 0; b < 4; b++) {
      float f[16];
      cvt4_e4m3(f,      wv[b].x);
      cvt4_e4m3(f + 4,  wv[b].y);
      cvt4_e4m3(f + 8,  wv[b].z);
      cvt4_e4m3(f + 12, wv[b].w);
      float q2 = 0.0f;
#pragma unroll
      for (int i = 0; i < 16; i++) {
        sA[i] += f[i];
        uA[i] = fmaf(tv[b], f[i], uA[i]);
        q2 = fmaf(f[i], f[i], q2);
      }
      nrm = fmaf(tv[b], q2, nrm);
    }
  }

  // merge lane pairs (hi=0/1 hold the same 16 cols, different rows)
#pragma unroll
  for (int i = 0; i < 16; i++) {
    sA[i] += __shfl_xor_sync(0xffffffffu, sA[i], 16);
    uA[i] += __shfl_xor_sync(0xffffffffu, uA[i], 16);
  }
  if (hi == 0) {
#pragma unroll
    for (int i = 0; i < 16; i++) {
      sS[wid][l16 * 16 + i] = sA[i];
      sU[wid][l16 * 16 + i] = uA[i];
    }
  }

  // t^2 partial (quarter 0 only)
  float tsq = 0.0f;
  if (by == 0)
    for (int rr = tid; rr < g; rr += 512) { float t = sTv[rr]; tsq = fmaf(t, t, tsq); }
  __syncthreads();

  // dot partial: threads 0..255 own one column each; fixed-order 16-warp sum
  float dot = 0.0f;
  if (tid < 256) {
    float sv = 0.0f, uv = 0.0f;
#pragma unroll
    for (int w = 0; w < 16; w++) { sv += sS[w][tid]; uv += sU[w][tid]; }
    dot = sv * uv;
  }

  // all terms linear in per-thread partials -> single block reduce
  const float coef = 2.0f / ((float)CC * PSCALE * PSCALE);
  float local = (float)(g - 1) * tsq - coef * (dot - nrm);
  if (g == 0) local = 0.0f;

  local = warpSumf(local);
  if (lid == 0) rs[wid] = local;
  __syncthreads();
  float total = 0.0f;
  if (tid == 0) {
#pragma unroll
    for (int w = 0; w < 16; w++) total += rs[w];
    g_partial[c * NQ + by] = total;
    __threadfence();
    int old = atomicAdd(&g_done, 1);
    sLast = (old == NCLS * NQ - 1) ? 1 : 0;
  }
  __syncthreads();
  if (sLast) {
    float s = 0.0f;
    for (int i = tid; i < NCLS * NQ; i += 512) s += g_partial[i];
    s = warpSumf(s);
    if (lid == 0) rs[wid] = s;
    __syncthreads();
    if (tid == 0) {
      float tot = 0.0f;
#pragma unroll
      for (int w = 0; w < 16; w++) tot += rs[w];
      out[0] = tot / (float)BB;
      g_done = 0;             // reset for next graph replay
    }
  }
}

extern "C" void kernel_launch(void* const* d_in, const int* in_sizes, int n_in,
                              void* d_out, int out_size) {
  const float* x;
  const int* tgt32;
  if (in_sizes[0] == BB) {       // defensive input-order detection
    tgt32 = (const int*)d_in[0];
    x     = (const float*)d_in[1];
  } else {
    x     = (const float*)d_in[0];
    tgt32 = (const int*)d_in[1];
  }

  softmax_kernel<<<BB / 8, 256>>>(x, tgt32);
  dim3 gr(NCLS, NQ);
  reduce_kernel<<<gr, 512>>>((float*)d_out);
}

// round 16
// speedup vs baseline: 1.1530x; 1.1530x over previous
#include <cuda_runtime.h>
#include <cuda_bf16.h>
#include <cstdint>

#define BB    8192
#define CC    1024
#define NCLS  100
#define CAP   1024
#define NQ    8          // column eighths for the reduce kernel
#define TINV  0.25f      // 1/T, T=4
#define PSCALE 128.0f    // fp8 storage scale: q = p*128 keeps q in e4m3 normal range

// ---- scratch (device globals: no allocations allowed) ----
__device__ uint8_t g_p8[(size_t)BB * CC];         // 8 MB fp8(e4m3) scaled probs
__device__ float g_t[BB];
__device__ int   g_cnt[NCLS];
__device__ int   g_list[NCLS * CAP];
__device__ float g_partial[NCLS * NQ];
__device__ int   g_done = 0;                      // reset by last CTA each run

// ---- helpers ----
__device__ __forceinline__ uint32_t pack4_e4m3(float p0, float p1, float p2, float p3) {
  uint16_t lo, hi;
  asm("cvt.rn.satfinite.e4m3x2.f32 %0, %1, %2;" : "=h"(lo) : "f"(p1), "f"(p0));
  asm("cvt.rn.satfinite.e4m3x2.f32 %0, %1, %2;" : "=h"(hi) : "f"(p3), "f"(p2));
  return (uint32_t)lo | ((uint32_t)hi << 16);
}

// 4 e4m3 bytes (one uint32) -> 4 floats. Exact: e4m3 -> f16 -> f32.
// Column-order permutation inside the word is irrelevant (all uses are
// column-symmetric sums with consistent s/u pairing).
__device__ __forceinline__ void cvt4_e4m3(float* f, uint32_t w) {
  uint32_t h0, h1;
  asm("cvt.rn.f16x2.e4m3x2 %0, %1;" : "=r"(h0) : "h"((uint16_t)(w & 0xffff)));
  asm("cvt.rn.f16x2.e4m3x2 %0, %1;" : "=r"(h1) : "h"((uint16_t)(w >> 16)));
  asm("{.reg .f16 l, h; mov.b32 {l, h}, %2; cvt.f32.f16 %0, l; cvt.f32.f16 %1, h;}"
      : "=f"(f[0]), "=f"(f[1]) : "r"(h0));
  asm("{.reg .f16 l, h; mov.b32 {l, h}, %2; cvt.f32.f16 %0, l; cvt.f32.f16 %1, h;}"
      : "=f"(f[2]), "=f"(f[3]) : "r"(h1));
}

__device__ __forceinline__ float warpMaxf(float v) {
#pragma unroll
  for (int o = 16; o > 0; o >>= 1) v = fmaxf(v, __shfl_xor_sync(0xffffffffu, v, o));
  return v;
}
__device__ __forceinline__ float warpSumf(float v) {
#pragma unroll
  for (int o = 16; o > 0; o >>= 1) v += __shfl_xor_sync(0xffffffffu, v, o);
  return v;
}

// exp(z) for z <= 0 via 2^w with degree-7 poly: FMA pipe only, avoids MUFU.EX2.
__device__ __forceinline__ float fast_exp(float z) {
  float w  = z * 1.4426950408889634f;
  float nf = floorf(w);
  float f  = w - nf;
  float r  = 1.5252733e-5f;
  r = fmaf(r, f, 1.5403530e-4f);
  r = fmaf(r, f, 1.3333558e-3f);
  r = fmaf(r, f, 9.6181291e-3f);
  r = fmaf(r, f, 5.5504109e-2f);
  r = fmaf(r, f, 2.4022651e-1f);
  r = fmaf(r, f, 6.9314718e-1f);
  r = fmaf(r, f, 1.0f);
  return r * __int_as_float(((int)nf + 127) << 23);
}

// ---- setup (runs inside softmax CTA 0): dtype probe + class scatter ----
// JAX with x64 disabled silently stores int64-requested targets as int32.
// True LE int64 in [0,100) => every odd 32-bit word of the first BB words is 0.
__device__ __forceinline__ void do_setup(const int* __restrict__ tgt32, int tid) {
  __shared__ int scnt[NCLS];
  __shared__ int nz;
  for (int i = tid; i < NCLS; i += 256) scnt[i] = 0;
  if (tid == 0) nz = 0;
  __syncthreads();

  int c = 0;
  for (int i = tid; i < BB / 2; i += 256)
    if (tgt32[2 * i + 1] != 0) c++;
  if (c) atomicAdd(&nz, 1);
  __syncthreads();
  int stride = (nz == 0) ? 2 : 1;   // 2 => int64 low words

  for (int i = tid; i < BB; i += 256) {
    int cl = tgt32[(size_t)i * stride];
    if ((unsigned)cl < NCLS) {
      int s = atomicAdd(&scnt[cl], 1);
      if (s < CAP) g_list[cl * CAP + s] = i;
    }
  }
  __syncthreads();
  for (int i = tid; i < NCLS; i += 256) g_cnt[i] = scnt[i];
}

// ---------------- softmax + t (warp per row) + embedded setup in CTA 0 ----------------
__global__ void __launch_bounds__(256) softmax_kernel(const float* __restrict__ x,
                                                      const int* __restrict__ tgt32) {
  if (blockIdx.x == 0) do_setup(tgt32, threadIdx.x);

  int wid = threadIdx.x >> 5, lid = threadIdx.x & 31;
  int row = blockIdx.x * 8 + wid;

  const float4* src = reinterpret_cast<const float4*>(x + (size_t)row * CC);
  float y[32];
  float m = -3.4e38f;
#pragma unroll
  for (int q = 0; q < 8; q++) {
    float4 v = src[q * 32 + lid];
    y[4 * q + 0] = v.x * TINV; y[4 * q + 1] = v.y * TINV;
    y[4 * q + 2] = v.z * TINV; y[4 * q + 3] = v.w * TINV;
    m = fmaxf(m, fmaxf(fmaxf(y[4 * q], y[4 * q + 1]), fmaxf(y[4 * q + 2], y[4 * q + 3])));
  }
  m = warpMaxf(m);

  float e[32];
  float s = 0.0f;
#pragma unroll
  for (int i = 0; i < 32; i++) { e[i] = fast_exp(y[i] - m); s += e[i]; }
  s = warpSumf(s);
  float invS = 1.0f / s;
  float lnS  = __logf(s);

  uint32_t* dst = reinterpret_cast<uint32_t*>(g_p8 + (size_t)row * CC);
  float tl = 0.0f;
#pragma unroll
  for (int q = 0; q < 8; q++) {
    float p0 = fmaf(e[4 * q + 0], invS, 1e-8f);
    float p1 = fmaf(e[4 * q + 1], invS, 1e-8f);
    float p2 = fmaf(e[4 * q + 2], invS, 1e-8f);
    float p3 = fmaf(e[4 * q + 3], invS, 1e-8f);
    // log p ~= y - m - lnS (+1e-8 shift perturbs log by ~1e-5 abs -> negligible)
    tl += p0 * (y[4 * q + 0] - m - lnS) + p1 * (y[4 * q + 1] - m - lnS)
        + p2 * (y[4 * q + 2] - m - lnS) + p3 * (y[4 * q + 3] - m - lnS);
    dst[q * 32 + lid] = pack4_e4m3(p0 * PSCALE, p1 * PSCALE, p2 * PSCALE, p3 * PSCALE);
  }
  tl = warpSumf(tl);
  if (lid == 0) g_t[row] = tl * (1.0f / CC);
}

// ------------- per-(class, column-eighth) linearized loss + fused final reduce ------
// Loss per class over ordered same-label pairs (i != j):
//   sum (t_j - cross_ij)^2 = (g-1)*sum t^2 - (2/C)*( s.u - sum_j t_j*||p_j||^2 )
//                            [ + sum cross^2, ~2e-8 rel: dropped ]
// grid = (NCLS, NQ): CTA (c, by) owns 128 columns. Warp w handles rows w, w+16,...
// all 32 lanes read ONE row's contiguous 128 B (1 wavefront per LDG.32 -- the
// R14 layout that profiled best); 4 rows' loads batched with predicated zero-fill
// BEFORE any conversion => per-thread chain ~2 exposed DRAM round-trips (R14's
// binder was a ~10-deep MLP=2 chain).
__global__ void __launch_bounds__(512) reduce_kernel(float* __restrict__ out) {
  int c  = blockIdx.x;
  int by = blockIdx.y;
  int g  = min(g_cnt[c], CAP);

  __shared__ float sS[16][128];   // 8 KB per-warp s partials (128 cols)
  __shared__ float sU[16][128];   // 8 KB
  __shared__ int   sRow[CAP];     // 4 KB
  __shared__ float sTv[CAP];      // 4 KB
  __shared__ float rs[16];
  __shared__ int   sLast;

  int tid = threadIdx.x, wid = tid >> 5, lid = tid & 31;
  int wordoff = by * 32;          // eighth offset in words (4 fp8 cols per word)

  for (int r = tid; r < g; r += 512) {
    int ro = g_list[c * CAP + r];
    sRow[r] = ro;
    sTv[r]  = g_t[ro];
  }
  __syncthreads();

  float sA[4], uA[4];
#pragma unroll
  for (int i = 0; i < 4; i++) { sA[i] = 0.0f; uA[i] = 0.0f; }
  float nrm = 0.0f;   // partial: sum_j t_j * (lane part of ||q_j||^2)

  // warp w owns rows w, w+16, ...; 4 rows batched per iteration (MLP=4)
  for (int r = wid; r < g; r += 64) {
    uint32_t wv[4];
    float    tv[4];
#pragma unroll
    for (int b = 0; b < 4; b++) {
      int rr = r + 16 * b;
      bool v = rr < g;
      int ro = sRow[v ? rr : 0];
      wv[b] = v ? ((const uint32_t*)(g_p8 + (size_t)ro * CC))[wordoff + lid] : 0u;
      tv[b] = v ? sTv[rr] : 0.0f;
    }
#pragma unroll
    for (int b = 0; b < 4; b++) {
      float f[4];
      cvt4_e4m3(f, wv[b]);        // zero word -> zero contribution
      float q2 = 0.0f;
#pragma unroll
      for (int i = 0; i < 4; i++) {
        sA[i] += f[i];
        uA[i] = fmaf(tv[b], f[i], uA[i]);
        q2 = fmaf(f[i], f[i], q2);
      }
      nrm = fmaf(tv[b], q2, nrm);
    }
  }

  // t^2 partial (eighth 0 only)
  float tsq = 0.0f;
  if (by == 0)
    for (int rr = tid; rr < g; rr += 512) { float t = sTv[rr]; tsq = fmaf(t, t, tsq); }

  // publish per-warp s,u
#pragma unroll
  for (int i = 0; i < 4; i++) {
    sS[wid][4 * lid + i] = sA[i];
    sU[wid][4 * lid + i] = uA[i];
  }
  __syncthreads();

  // dot partial: threads 0..127 own one column each; fixed-order 16-warp sum
  float dot = 0.0f;
  if (tid < 128) {
    float sv = 0.0f, uv = 0.0f;
#pragma unroll
    for (int w = 0; w < 16; w++) { sv += sS[w][tid]; uv += sU[w][tid]; }
    dot = sv * uv;
  }

  // all terms linear in per-thread partials -> single block reduce
  const float coef = 2.0f / ((float)CC * PSCALE * PSCALE);
  float local = (float)(g - 1) * tsq - coef * (dot - nrm);
  if (g == 0) local = 0.0f;

  local = warpSumf(local);
  if (lid == 0) rs[wid] = local;
  __syncthreads();
  float total = 0.0f;
  if (tid == 0) {
#pragma unroll
    for (int w = 0; w < 16; w++) total += rs[w];
    g_partial[c * NQ + by] = total;
    __threadfence();
    int old = atomicAdd(&g_done, 1);
    sLast = (old == NCLS * NQ - 1) ? 1 : 0;
  }
  __syncthreads();
  if (sLast) {
    float s = 0.0f;
    for (int i = tid; i < NCLS * NQ; i += 512) s += g_partial[i];
    s = warpSumf(s);
    if (lid == 0) rs[wid] = s;
    __syncthreads();
    if (tid == 0) {
      float tot = 0.0f;
#pragma unroll
      for (int w = 0; w < 16; w++) tot += rs[w];
      out[0] = tot / (float)BB;
      g_done = 0;             // reset for next graph replay
    }
  }
}

extern "C" void kernel_launch(void* const* d_in, const int* in_sizes, int n_in,
                              void* d_out, int out_size) {
  const float* x;
  const int* tgt32;
  if (in_sizes[0] == BB) {       // defensive input-order detection
    tgt32 = (const int*)d_in[0];
    x     = (const float*)d_in[1];
  } else {
    x     = (const float*)d_in[0];
    tgt32 = (const int*)d_in[1];
  }

  softmax_kernel<<<BB / 8, 256>>>(x, tgt32);
  dim3 gr(NCLS, NQ);
  reduce_kernel<<<gr, 512>>>((float*)d_out);
}

// round 17
// speedup vs baseline: 1.1783x; 1.0220x over previous
#include <cuda_runtime.h>
#include <cuda_bf16.h>
#include <cstdint>

#define BB    8192
#define CC    1024
#define NCLS  100
#define CAP   1024
#define NQ    4          // column quarters for the reduce kernel
#define TINV  0.25f      // 1/T, T=4

// ---- scratch (device globals: no allocations allowed) ----
__device__ __nv_bfloat16 g_pb[(size_t)BB * CC];   // 16 MB bf16 probs
__device__ float g_t[BB];
__device__ int   g_cnt[NCLS];
__device__ int   g_list[NCLS * CAP];
__device__ float g_partial[NCLS * NQ];
__device__ int   g_done = 0;                      // reset by last CTA each run

typedef unsigned long long ull;

// ---- packed f32x2 helpers ----
__device__ __forceinline__ void ffma2(ull& d, ull a, ull b) {        // d = a*b + d
  asm("fma.rn.f32x2 %0, %1, %2, %0;" : "+l"(d) : "l"(a), "l"(b));
}
__device__ __forceinline__ void fadd2(ull& d, ull a) {               // d = d + a
  asm("add.rn.f32x2 %0, %0, %1;" : "+l"(d) : "l"(a));
}
__device__ __forceinline__ ull pack2(float lo, float hi) {
  ull d;
  asm("mov.b64 %0, {%1, %2};" : "=l"(d) : "f"(lo), "f"(hi));
  return d;
}
__device__ __forceinline__ void unpack2(float& lo, float& hi, ull v) {
  asm("mov.b64 {%0, %1}, %2;" : "=f"(lo), "=f"(hi) : "l"(v));
}
// one uint32 holding 2 bf16 -> packed f32x2 (exact: f32 = bf16 << 16)
__device__ __forceinline__ ull bf2_to_f32x2(uint32_t w) {
  uint32_t f0 = w << 16;
  uint32_t f1 = w & 0xffff0000u;
  ull d;
  asm("mov.b64 %0, {%1, %2};" : "=l"(d) : "r"(f0), "r"(f1));
  return d;
}

__device__ __forceinline__ float warpMaxf(float v) {
#pragma unroll
  for (int o = 16; o > 0; o >>= 1) v = fmaxf(v, __shfl_xor_sync(0xffffffffu, v, o));
  return v;
}
__device__ __forceinline__ float warpSumf(float v) {
#pragma unroll
  for (int o = 16; o > 0; o >>= 1) v += __shfl_xor_sync(0xffffffffu, v, o);
  return v;
}

// exp(z) for z <= 0 via 2^w with degree-7 poly: FMA pipe only, avoids MUFU.EX2.
__device__ __forceinline__ float fast_exp(float z) {
  float w  = z * 1.4426950408889634f;
  float nf = floorf(w);
  float f  = w - nf;
  float r  = 1.5252733e-5f;
  r = fmaf(r, f, 1.5403530e-4f);
  r = fmaf(r, f, 1.3333558e-3f);
  r = fmaf(r, f, 9.6181291e-3f);
  r = fmaf(r, f, 5.5504109e-2f);
  r = fmaf(r, f, 2.4022651e-1f);
  r = fmaf(r, f, 6.9314718e-1f);
  r = fmaf(r, f, 1.0f);
  return r * __int_as_float(((int)nf + 127) << 23);
}

// ---- setup (runs inside softmax CTA 0): dtype probe + class scatter ----
// JAX with x64 disabled silently stores int64-requested targets as int32.
// True LE int64 in [0,100) => every odd 32-bit word of the first BB words is 0.
__device__ __forceinline__ void do_setup(const int* __restrict__ tgt32, int tid) {
  __shared__ int scnt[NCLS];
  __shared__ int nz;
  for (int i = tid; i < NCLS; i += 256) scnt[i] = 0;
  if (tid == 0) nz = 0;
  __syncthreads();

  int c = 0;
  for (int i = tid; i < BB / 2; i += 256)
    if (tgt32[2 * i + 1] != 0) c++;
  if (c) atomicAdd(&nz, 1);
  __syncthreads();
  int stride = (nz == 0) ? 2 : 1;   // 2 => int64 low words

  for (int i = tid; i < BB; i += 256) {
    int cl = tgt32[(size_t)i * stride];
    if ((unsigned)cl < NCLS) {
      int s = atomicAdd(&scnt[cl], 1);
      if (s < CAP) g_list[cl * CAP + s] = i;
    }
  }
  __syncthreads();
  for (int i = tid; i < NCLS; i += 256) g_cnt[i] = scnt[i];
}

// ---------------- softmax + t (warp per row) + embedded setup in CTA 0 ----------------
__global__ void __launch_bounds__(256) softmax_kernel(const float* __restrict__ x,
                                                      const int* __restrict__ tgt32) {
  if (blockIdx.x == 0) do_setup(tgt32, threadIdx.x);

  int wid = threadIdx.x >> 5, lid = threadIdx.x & 31;
  int row = blockIdx.x * 8 + wid;

  const float4* src = reinterpret_cast<const float4*>(x + (size_t)row * CC);
  float y[32];
  float m = -3.4e38f;
#pragma unroll
  for (int q = 0; q < 8; q++) {
    float4 v = src[q * 32 + lid];
    y[4 * q + 0] = v.x * TINV; y[4 * q + 1] = v.y * TINV;
    y[4 * q + 2] = v.z * TINV; y[4 * q + 3] = v.w * TINV;
    m = fmaxf(m, fmaxf(fmaxf(y[4 * q], y[4 * q + 1]), fmaxf(y[4 * q + 2], y[4 * q + 3])));
  }
  m = warpMaxf(m);

  float e[32];
  float s = 0.0f;
#pragma unroll
  for (int i = 0; i < 32; i++) { e[i] = fast_exp(y[i] - m); s += e[i]; }
  s = warpSumf(s);
  float invS = 1.0f / s;
  float lnS  = __logf(s);

  uint2* dst = reinterpret_cast<uint2*>(g_pb + (size_t)row * CC);
  float tl = 0.0f;
#pragma unroll
  for (int q = 0; q < 8; q++) {
    float p0 = fmaf(e[4 * q + 0], invS, 1e-8f);
    float p1 = fmaf(e[4 * q + 1], invS, 1e-8f);
    float p2 = fmaf(e[4 * q + 2], invS, 1e-8f);
    float p3 = fmaf(e[4 * q + 3], invS, 1e-8f);
    // log p ~= y - m - lnS (+1e-8 shift perturbs log by ~1e-5 abs -> negligible)
    tl += p0 * (y[4 * q + 0] - m - lnS) + p1 * (y[4 * q + 1] - m - lnS)
        + p2 * (y[4 * q + 2] - m - lnS) + p3 * (y[4 * q + 3] - m - lnS);
    __nv_bfloat162 h01 = __floats2bfloat162_rn(p0, p1);
    __nv_bfloat162 h23 = __floats2bfloat162_rn(p2, p3);
    uint2 pk;
    pk.x = *reinterpret_cast<uint32_t*>(&h01);
    pk.y = *reinterpret_cast<uint32_t*>(&h23);
    dst[q * 32 + lid] = pk;
  }
  tl = warpSumf(tl);
  if (lid == 0) g_t[row] = tl * (1.0f / CC);
}

// ------------- per-(class, column-quarter) linearized loss + fused final reduce ------
// Loss per class over ordered same-label pairs (i != j):
//   sum (t_j - cross_ij)^2 = (g-1)*sum t^2 - (2/C)*( s.u - sum_j t_j*||p_j||^2 )
//                            [ + sum cross^2, ~2e-8 rel: dropped ]
// grid = (NCLS, NQ): CTA (c, by) owns 256 columns. Warp w handles rows w, w+16,...
// Lane reads ONE uint4 = 8 contiguous bf16 cols of one row (all 32 lanes cover the
// 512B quarter of one row). 4 rows' gathers batched (predicated zero-fill) BEFORE
// decode => ~2 exposed DRAM round-trips. Decode = shift/mask (ALU), accumulate via
// packed f32x2 FMA: ~2.5 ops/value vs fp8's ~4.8 (the R16 instruction binder).
__global__ void __launch_bounds__(512) reduce_kernel(float* __restrict__ out) {
  int c  = blockIdx.x;
  int by = blockIdx.y;
  int g  = min(g_cnt[c], CAP);

  __shared__ float sS[16][256];   // 16 KB per-warp s partials (256 cols)
  __shared__ float sU[16][256];   // 16 KB
  __shared__ int   sRow[CAP];     // 4 KB
  __shared__ float sTv[CAP];      // 4 KB
  __shared__ float rs[16];
  __shared__ int   sLast;

  int tid = threadIdx.x, wid = tid >> 5, lid = tid & 31;
  int qidx = by * 32 + lid;       // uint4 index within row (128 per 2048B row)

  for (int r = tid; r < g; r += 512) {
    int ro = g_list[c * CAP + r];
    sRow[r] = ro;
    sTv[r]  = g_t[ro];
  }
  __syncthreads();

  ull sA[4], uA[4];               // packed f32x2 accumulators (8 cols per lane)
#pragma unroll
  for (int i = 0; i < 4; i++) { sA[i] = 0ull; uA[i] = 0ull; }
  float nrm = 0.0f;               // partial: sum_j t_j * (lane part of ||p_j||^2)

  // warp w owns rows w, w+16, ...; 4 rows batched per iteration (MLP=4)
  for (int r = wid; r < g; r += 64) {
    uint4 wv[4];
    float tv[4];
#pragma unroll
    for (int b = 0; b < 4; b++) {
      int rr = r + 16 * b;
      bool v = rr < g;
      int ro = sRow[v ? rr : 0];
      wv[b] = v ? reinterpret_cast<const uint4*>(g_pb + (size_t)ro * CC)[qidx]
                : make_uint4(0u, 0u, 0u, 0u);
      tv[b] = v ? sTv[rr] : 0.0f;
    }
#pragma unroll
    for (int b = 0; b < 4; b++) {
      ull p[4];
      p[0] = bf2_to_f32x2(wv[b].x);
      p[1] = bf2_to_f32x2(wv[b].y);
      p[2] = bf2_to_f32x2(wv[b].z);
      p[3] = bf2_to_f32x2(wv[b].w);
      ull tp = pack2(tv[b], tv[b]);
      ull q2 = 0ull;
#pragma unroll
      for (int i = 0; i < 4; i++) {
        fadd2(sA[i], p[i]);
        ffma2(uA[i], tp, p[i]);
        ffma2(q2, p[i], p[i]);
      }
      float qlo, qhi;
      unpack2(qlo, qhi, q2);
      nrm = fmaf(tv[b], qlo + qhi, nrm);
    }
  }

  // t^2 partial (quarter 0 only)
  float tsq = 0.0f;
  if (by == 0)
    for (int rr = tid; rr < g; rr += 512) { float t = sTv[rr]; tsq = fmaf(t, t, tsq); }

  // publish per-warp s,u (lane owns quarter-local cols lid*8 .. lid*8+7)
#pragma unroll
  for (int i = 0; i < 4; i++) {
    float lo, hi;
    unpack2(lo, hi, sA[i]);
    sS[wid][lid * 8 + 2 * i]     = lo;
    sS[wid][lid * 8 + 2 * i + 1] = hi;
    unpack2(lo, hi, uA[i]);
    sU[wid][lid * 8 + 2 * i]     = lo;
    sU[wid][lid * 8 + 2 * i + 1] = hi;
  }
  __syncthreads();

  // dot partial: threads 0..255 own one column each; fixed-order 16-warp sum
  float dot = 0.0f;
  if (tid < 256) {
    float sv = 0.0f, uv = 0.0f;
#pragma unroll
    for (int w = 0; w < 16; w++) { sv += sS[w][tid]; uv += sU[w][tid]; }
    dot = sv * uv;
  }

  // all terms linear in per-thread partials -> single block reduce
  const float coef = 2.0f / (float)CC;
  float local = (float)(g - 1) * tsq - coef * (dot - nrm);
  if (g == 0) local = 0.0f;

  local = warpSumf(local);
  if (lid == 0) rs[wid] = local;
  __syncthreads();
  float total = 0.0f;
  if (tid == 0) {
#pragma unroll
    for (int w = 0; w < 16; w++) total += rs[w];
    g_partial[c * NQ + by] = total;
    __threadfence();
    int old = atomicAdd(&g_done, 1);
    sLast = (old == NCLS * NQ - 1) ? 1 : 0;
  }
  __syncthreads();
  if (sLast) {
    float s = 0.0f;
    for (int i = tid; i < NCLS * NQ; i += 512) s += g_partial[i];
    s = warpSumf(s);
    if (lid == 0) rs[wid] = s;
    __syncthreads();
    if (tid == 0) {
      float tot = 0.0f;
#pragma unroll
      for (int w = 0; w < 16; w++) tot += rs[w];
      out[0] = tot / (float)BB;
      g_done = 0;             // reset for next graph replay
    }
  }
}

extern "C" void kernel_launch(void* const* d_in, const int* in_sizes, int n_in,
                              void* d_out, int out_size) {
  const float* x;
  const int* tgt32;
  if (in_sizes[0] == BB) {       // defensive input-order detection
    tgt32 = (const int*)d_in[0];
    x     = (const float*)d_in[1];
  } else {
    x     = (const float*)d_in[0];
    tgt32 = (const int*)d_in[1];
  }

  softmax_kernel<<<BB / 8, 256>>>(x, tgt32);
  dim3 gr(NCLS, NQ);
  reduce_kernel<<<gr, 512>>>((float*)d_out);
}